// round 12
// baseline (speedup 1.0000x reference)
#include <cuda_runtime.h>

// ---------------------------------------------------------------------------
// Tree3 fused, round 12: R11 + phase-2 float4 weight loads.
// Lanes = float4-of-k (idx<105, m=idx/7, j=idx%7): tree_w LDG instruction
// count per gi drops 240 -> 64 (LDG.128 coalesced); FFMA2 count unchanged.
// Conv / reduction / FC phases identical to R11 (best).
// ---------------------------------------------------------------------------

#define THREADS 256
#define BTOT 2048

// float2-unit strides
#define IMG_ROW_F2   34
#define IMG_PLANE_F2 1092
#define POOL_ROW_F2  15
#define POOL_CH_F2   211

#define SZ_IMG_F2    (3*IMG_PLANE_F2)
#define SZ_POOL_F2   (45*POOL_CH_F2)
#define OFF_POOL_F2  SZ_IMG_F2
#define OFF_W        (2*(SZ_IMG_F2 + SZ_POOL_F2))
#define OFF_CB       (OFF_W + 1128)
#define OFF_T        (OFF_CB + 48)
#define SMEM_FLOATS  (OFF_T + 2*336)

__device__ __forceinline__ float2 ffma2(float2 a, float2 b, float2 c) {
    unsigned long long au = *reinterpret_cast<unsigned long long*>(&a);
    unsigned long long bu = *reinterpret_cast<unsigned long long*>(&b);
    unsigned long long cu = *reinterpret_cast<unsigned long long*>(&c);
    unsigned long long du;
    asm("fma.rn.f32x2 %0, %1, %2, %3;" : "=l"(du) : "l"(au), "l"(bu), "l"(cu));
    return *reinterpret_cast<float2*>(&du);
}

__device__ __forceinline__ float sigmoidf_fast(float v) {
    return __fdividef(1.0f, 1.0f + __expf(-v));
}

// One column-subpass of the 5x5 conv over an image pair (proven form)
template<int NC>
__device__ __forceinline__ void conv_subpass(const float2* __restrict__ ib,
                                             const float*  __restrict__ wb,
                                             float2* __restrict__ pmax)
{
    constexpr int NF4 = (NC + 5) / 2;
    float2 acc0[NC], acc1[NC];
    #pragma unroll
    for (int k = 0; k < NC; k++) {
        acc0[k] = make_float2(0.f, 0.f);
        acc1[k] = make_float2(0.f, 0.f);
    }

    float2 wpk[5];
    #pragma unroll
    for (int r = 0; r < 6; r++) {
        float2 P[2 * NF4];
        const float4* rp = (const float4*)(ib + r * IMG_ROW_F2);
        #pragma unroll
        for (int u = 0; u < NF4; u++) {
            float4 q = rp[u];
            P[2*u]   = make_float2(q.x, q.y);
            P[2*u+1] = make_float2(q.z, q.w);
        }
        if (r > 0) {
            #pragma unroll
            for (int kx = 0; kx < 5; kx++)
                #pragma unroll
                for (int ox = 0; ox < NC; ox++)
                    acc1[ox] = ffma2(P[ox + kx], wpk[kx], acc1[ox]);
        }
        if (r < 5) {
            #pragma unroll
            for (int kx = 0; kx < 5; kx++) {
                float w = wb[r * 5 + kx];
                wpk[kx] = make_float2(w, w);
            }
            #pragma unroll
            for (int kx = 0; kx < 5; kx++)
                #pragma unroll
                for (int ox = 0; ox < NC; ox++)
                    acc0[ox] = ffma2(P[ox + kx], wpk[kx], acc0[ox]);
        }
    }

    #pragma unroll
    for (int pj = 0; pj < NC / 2; pj++) {
        float vx = fmaxf(fmaxf(acc0[2*pj].x, acc0[2*pj+1].x),
                         fmaxf(acc1[2*pj].x, acc1[2*pj+1].x));
        float vy = fmaxf(fmaxf(acc0[2*pj].y, acc0[2*pj+1].y),
                         fmaxf(acc1[2*pj].y, acc1[2*pj+1].y));
        pmax[pj] = make_float2(vx, vy);
    }
}

__global__ __launch_bounds__(THREADS, 2)
void tree3_fused(const float* __restrict__ x,
                 const float* __restrict__ conv_w,
                 const float* __restrict__ conv_b,
                 const float* __restrict__ tree_w,
                 const float* __restrict__ tree_b,
                 const float* __restrict__ fc_w,
                 const float* __restrict__ fc_b,
                 float* __restrict__ out)
{
    extern __shared__ __align__(16) float sm[];
    float2* s_img  = reinterpret_cast<float2*>(sm);
    float2* s_pool = reinterpret_cast<float2*>(sm) + OFF_POOL_F2;
    float*  s_w    = sm + OFF_W;
    float*  s_cb   = sm + OFF_CB;
    float*  s_t    = sm + OFF_T;

    const int tid  = threadIdx.x;
    const int lane = tid & 31;
    const int wid  = tid >> 5;
    const int b0   = blockIdx.x * 2;

    // ---- stage conv weights + bias ----
    for (int idx = tid; idx < 1125; idx += THREADS) s_w[idx] = conv_w[idx];
    if (tid < 45) s_cb[tid] = conv_b[tid];

    // ---- stage the image pair, interleaved (float4 in/out) ----
    for (int idx = tid; idx < 3 * 32 * 8; idx += THREADS) {
        int grp = idx & 7;
        int row = (idx >> 3) & 31;
        int gch = idx >> 8;
        const float* pA = x + (size_t)b0 * 3072 + gch * 1024 + row * 32 + grp * 4;
        float4 a = *(const float4*)pA;
        float4 b = *(const float4*)(pA + 3072);
        float4* dst = (float4*)(s_img + gch * IMG_PLANE_F2
                                      + row * IMG_ROW_F2 + grp * 4);
        dst[0] = make_float4(a.x, b.x, a.y, b.y);
        dst[1] = make_float4(a.z, b.z, a.w, b.w);
    }
    __syncthreads();

    // ---- phase 1: packed conv + sigmoid(max-pool) ----
    for (int task = tid; task < 45 * 28; task += THREADS) {
        int c    = task % 45;
        int rest = task / 45;
        int half = rest & 1;
        int pi   = rest >> 1;

        int g  = c / 15;
        const float*  wb = s_w + c * 25;
        const float2* ib = s_img + g * IMG_PLANE_F2
                                 + (pi * 2) * IMG_ROW_F2 + half * 14;

        float2 pmax[7];
        conv_subpass<8>(ib,     wb, pmax);
        conv_subpass<6>(ib + 8, wb, pmax + 4);

        float bias = s_cb[c];
        float2* pb = s_pool + c * POOL_CH_F2 + pi * POOL_ROW_F2 + half * 7;
        #pragma unroll
        for (int pj = 0; pj < 7; pj++)
            pb[pj] = make_float2(sigmoidf_fast(pmax[pj].x + bias),
                                 sigmoidf_fast(pmax[pj].y + bias));
    }
    __syncthreads();

    // ---- phase 2: tree einsum, one warp per gi, lanes = float4-of-k ----
    // idx = lane + 32t (t<4), valid idx < 105; m = idx/7, j = idx%7.
    // weight float4 covers (ki,kj) quad <-> pool[2i+ki][2j+kj].
    for (int gi = wid; gi < 21; gi += THREADS / 32) {
        int g = gi / 7;
        int i = gi % 7;

        const float* wbase = tree_w + g * 196 + i * 28;  // + f*8820 + m*588 + j*4
        const float2* pb0  = s_pool + (g * 15) * POOL_CH_F2
                                    + (2 * i) * POOL_ROW_F2;

        float2 acc[16];
        #pragma unroll
        for (int f = 0; f < 16; f++) acc[f] = make_float2(0.f, 0.f);

        #pragma unroll
        for (int t = 0; t < 4; t++) {
            int idx = lane + 32 * t;
            if (idx < 105) {
                int m = idx / 7;
                int j = idx - 7 * m;

                int po = m * POOL_CH_F2 + 2 * j;
                float2 p00 = pb0[po];
                float2 p01 = pb0[po + 1];
                float2 p10 = pb0[po + POOL_ROW_F2];
                float2 p11 = pb0[po + POOL_ROW_F2 + 1];

                const float4* wl = reinterpret_cast<const float4*>(
                                       wbase + m * 588 + j * 4);
                #pragma unroll
                for (int f = 0; f < 16; f++) {
                    float4 w = __ldg(wl + f * 2205);
                    acc[f] = ffma2(p00, make_float2(w.x, w.x), acc[f]);
                    acc[f] = ffma2(p01, make_float2(w.y, w.y), acc[f]);
                    acc[f] = ffma2(p10, make_float2(w.z, w.z), acc[f]);
                    acc[f] = ffma2(p11, make_float2(w.w, w.w), acc[f]);
                }
            }
        }

        // select-butterfly: 16 sums over 32 lanes in 4 halving steps + 1
        {
            bool b = (lane & 16) != 0;
            #pragma unroll
            for (int f = 0; f < 8; f++) {
                float2 snd = b ? acc[f] : acc[f + 8];
                float rx = __shfl_xor_sync(0xffffffffu, snd.x, 16);
                float ry = __shfl_xor_sync(0xffffffffu, snd.y, 16);
                float2 kp = b ? acc[f + 8] : acc[f];
                acc[f] = make_float2(kp.x + rx, kp.y + ry);
            }
        }
        {
            bool b = (lane & 8) != 0;
            #pragma unroll
            for (int f = 0; f < 4; f++) {
                float2 snd = b ? acc[f] : acc[f + 4];
                float rx = __shfl_xor_sync(0xffffffffu, snd.x, 8);
                float ry = __shfl_xor_sync(0xffffffffu, snd.y, 8);
                float2 kp = b ? acc[f + 4] : acc[f];
                acc[f] = make_float2(kp.x + rx, kp.y + ry);
            }
        }
        {
            bool b = (lane & 4) != 0;
            #pragma unroll
            for (int f = 0; f < 2; f++) {
                float2 snd = b ? acc[f] : acc[f + 2];
                float rx = __shfl_xor_sync(0xffffffffu, snd.x, 4);
                float ry = __shfl_xor_sync(0xffffffffu, snd.y, 4);
                float2 kp = b ? acc[f + 2] : acc[f];
                acc[f] = make_float2(kp.x + rx, kp.y + ry);
            }
        }
        {
            bool b = (lane & 2) != 0;
            float2 snd = b ? acc[0] : acc[1];
            float rx = __shfl_xor_sync(0xffffffffu, snd.x, 2);
            float ry = __shfl_xor_sync(0xffffffffu, snd.y, 2);
            float2 kp = b ? acc[1] : acc[0];
            acc[0] = make_float2(kp.x + rx, kp.y + ry);
        }
        acc[0].x += __shfl_xor_sync(0xffffffffu, acc[0].x, 1);
        acc[0].y += __shfl_xor_sync(0xffffffffu, acc[0].y, 1);

        // lane (f<<1) has f's sum; even lane stores img0, odd img1
        int f   = (lane >> 1) & 15;
        int idx = f * 21 + gi;
        float tb = tree_b[idx];
        if ((lane & 1) == 0)
            s_t[      idx] = sigmoidf_fast(acc[0].x + tb);
        else
            s_t[336 + idx] = sigmoidf_fast(acc[0].y + tb);
    }
    __syncthreads();

    // ---- phase 3: FC 336 -> 10 ----
    if (tid < 160) {
        int part  = tid & 7;
        int combo = tid >> 3;
        int img   = combo / 10;
        int o     = combo % 10;
        const float* tv = s_t + img * 336;
        const float* wv = fc_w + o * 336;
        float s = 0.f;
        for (int k = part; k < 336; k += 8)
            s = fmaf(tv[k], wv[k], s);
        s += __shfl_xor_sync(0xffffffffu, s, 1);
        s += __shfl_xor_sync(0xffffffffu, s, 2);
        s += __shfl_xor_sync(0xffffffffu, s, 4);
        if (part == 0)
            out[(b0 + img) * 10 + o] = s + fc_b[o];
    }
}

extern "C" void kernel_launch(void* const* d_in, const int* in_sizes, int n_in,
                              void* d_out, int out_size)
{
    const float* x      = (const float*)d_in[0];
    const float* conv_w = (const float*)d_in[1];
    const float* conv_b = (const float*)d_in[2];
    const float* tree_w = (const float*)d_in[3];
    const float* tree_b = (const float*)d_in[4];
    const float* fc_w   = (const float*)d_in[5];
    const float* fc_b   = (const float*)d_in[6];
    float* out = (float*)d_out;

    const int smem_bytes = SMEM_FLOATS * (int)sizeof(float);
    cudaFuncSetAttribute(tree3_fused,
                         cudaFuncAttributeMaxDynamicSharedMemorySize, smem_bytes);

    tree3_fused<<<BTOT / 2, THREADS, smem_bytes>>>(
        x, conv_w, conv_b, tree_w, tree_b, fc_w, fc_b, out);
}

// round 13
// speedup vs baseline: 1.0854x; 1.0854x over previous
#include <cuda_runtime.h>

// ---------------------------------------------------------------------------
// Tree3 fused, round 13: R11 (best) + phase-2 issue diet:
//  - m-loop fully unrolled -> all LDG/LDS use base+immediate, no pointer math
//  - tail lanes (28-31) handled by predicated FFMA2 (clamped in-bounds loads)
// Conv / reduction / FC phases identical to R11.
// ---------------------------------------------------------------------------

#define THREADS 256
#define BTOT 2048

// float2-unit strides
#define IMG_ROW_F2   34
#define IMG_PLANE_F2 1092
#define POOL_ROW_F2  15
#define POOL_CH_F2   211

#define SZ_IMG_F2    (3*IMG_PLANE_F2)
#define SZ_POOL_F2   (45*POOL_CH_F2)
#define OFF_POOL_F2  SZ_IMG_F2
#define OFF_W        (2*(SZ_IMG_F2 + SZ_POOL_F2))
#define OFF_CB       (OFF_W + 1128)
#define OFF_T        (OFF_CB + 48)
#define SMEM_FLOATS  (OFF_T + 2*336)

__device__ __forceinline__ float2 ffma2(float2 a, float2 b, float2 c) {
    unsigned long long au = *reinterpret_cast<unsigned long long*>(&a);
    unsigned long long bu = *reinterpret_cast<unsigned long long*>(&b);
    unsigned long long cu = *reinterpret_cast<unsigned long long*>(&c);
    unsigned long long du;
    asm("fma.rn.f32x2 %0, %1, %2, %3;" : "=l"(du) : "l"(au), "l"(bu), "l"(cu));
    return *reinterpret_cast<float2*>(&du);
}

__device__ __forceinline__ float sigmoidf_fast(float v) {
    return __fdividef(1.0f, 1.0f + __expf(-v));
}

// One column-subpass of the 5x5 conv over an image pair (proven form)
template<int NC>
__device__ __forceinline__ void conv_subpass(const float2* __restrict__ ib,
                                             const float*  __restrict__ wb,
                                             float2* __restrict__ pmax)
{
    constexpr int NF4 = (NC + 5) / 2;
    float2 acc0[NC], acc1[NC];
    #pragma unroll
    for (int k = 0; k < NC; k++) {
        acc0[k] = make_float2(0.f, 0.f);
        acc1[k] = make_float2(0.f, 0.f);
    }

    float2 wpk[5];
    #pragma unroll
    for (int r = 0; r < 6; r++) {
        float2 P[2 * NF4];
        const float4* rp = (const float4*)(ib + r * IMG_ROW_F2);
        #pragma unroll
        for (int u = 0; u < NF4; u++) {
            float4 q = rp[u];
            P[2*u]   = make_float2(q.x, q.y);
            P[2*u+1] = make_float2(q.z, q.w);
        }
        if (r > 0) {
            #pragma unroll
            for (int kx = 0; kx < 5; kx++)
                #pragma unroll
                for (int ox = 0; ox < NC; ox++)
                    acc1[ox] = ffma2(P[ox + kx], wpk[kx], acc1[ox]);
        }
        if (r < 5) {
            #pragma unroll
            for (int kx = 0; kx < 5; kx++) {
                float w = wb[r * 5 + kx];
                wpk[kx] = make_float2(w, w);
            }
            #pragma unroll
            for (int kx = 0; kx < 5; kx++)
                #pragma unroll
                for (int ox = 0; ox < NC; ox++)
                    acc0[ox] = ffma2(P[ox + kx], wpk[kx], acc0[ox]);
        }
    }

    #pragma unroll
    for (int pj = 0; pj < NC / 2; pj++) {
        float vx = fmaxf(fmaxf(acc0[2*pj].x, acc0[2*pj+1].x),
                         fmaxf(acc1[2*pj].x, acc1[2*pj+1].x));
        float vy = fmaxf(fmaxf(acc0[2*pj].y, acc0[2*pj+1].y),
                         fmaxf(acc1[2*pj].y, acc1[2*pj+1].y));
        pmax[pj] = make_float2(vx, vy);
    }
}

__global__ __launch_bounds__(THREADS, 2)
void tree3_fused(const float* __restrict__ x,
                 const float* __restrict__ conv_w,
                 const float* __restrict__ conv_b,
                 const float* __restrict__ tree_w,
                 const float* __restrict__ tree_b,
                 const float* __restrict__ fc_w,
                 const float* __restrict__ fc_b,
                 float* __restrict__ out)
{
    extern __shared__ __align__(16) float sm[];
    float2* s_img  = reinterpret_cast<float2*>(sm);
    float2* s_pool = reinterpret_cast<float2*>(sm) + OFF_POOL_F2;
    float*  s_w    = sm + OFF_W;
    float*  s_cb   = sm + OFF_CB;
    float*  s_t    = sm + OFF_T;

    const int tid  = threadIdx.x;
    const int lane = tid & 31;
    const int wid  = tid >> 5;
    const int b0   = blockIdx.x * 2;

    // ---- stage conv weights + bias ----
    for (int idx = tid; idx < 1125; idx += THREADS) s_w[idx] = conv_w[idx];
    if (tid < 45) s_cb[tid] = conv_b[tid];

    // ---- stage the image pair, interleaved (float4 in/out) ----
    for (int idx = tid; idx < 3 * 32 * 8; idx += THREADS) {
        int grp = idx & 7;
        int row = (idx >> 3) & 31;
        int gch = idx >> 8;
        const float* pA = x + (size_t)b0 * 3072 + gch * 1024 + row * 32 + grp * 4;
        float4 a = *(const float4*)pA;
        float4 b = *(const float4*)(pA + 3072);
        float4* dst = (float4*)(s_img + gch * IMG_PLANE_F2
                                      + row * IMG_ROW_F2 + grp * 4);
        dst[0] = make_float4(a.x, b.x, a.y, b.y);
        dst[1] = make_float4(a.z, b.z, a.w, b.w);
    }
    __syncthreads();

    // ---- phase 1: packed conv + sigmoid(max-pool) ----
    for (int task = tid; task < 45 * 28; task += THREADS) {
        int c    = task % 45;
        int rest = task / 45;
        int half = rest & 1;
        int pi   = rest >> 1;

        int g  = c / 15;
        const float*  wb = s_w + c * 25;
        const float2* ib = s_img + g * IMG_PLANE_F2
                                 + (pi * 2) * IMG_ROW_F2 + half * 14;

        float2 pmax[7];
        conv_subpass<8>(ib,     wb, pmax);
        conv_subpass<6>(ib + 8, wb, pmax + 4);

        float bias = s_cb[c];
        float2* pb = s_pool + c * POOL_CH_F2 + pi * POOL_ROW_F2 + half * 7;
        #pragma unroll
        for (int pj = 0; pj < 7; pj++)
            pb[pj] = make_float2(sigmoidf_fast(pmax[pj].x + bias),
                                 sigmoidf_fast(pmax[pj].y + bias));
    }
    __syncthreads();

    // ---- phase 2: tree einsum, one warp per gi, lanes = (j,ki,kj) ----
    {
        const bool act = lane < 28;
        const int jr  = lane >> 2;
        const int j   = (jr > 6) ? 6 : jr;     // clamp tail lanes in-bounds
        const int ki  = (lane >> 1) & 1;
        const int kj  = lane & 1;

        for (int gi = wid; gi < 21; gi += THREADS / 32) {
            int g = gi / 7;
            int i = gi % 7;

            // loop-invariant bases; all m/f offsets below are immediates
            const float* wl = tree_w + g * 196 + i * 28 + j * 4 + ki * 2 + kj;
            const float2* pl = s_pool + (g * 15) * POOL_CH_F2
                             + (2 * i + ki) * POOL_ROW_F2 + 2 * j + kj;

            float2 acc[16];
            #pragma unroll
            for (int f = 0; f < 16; f++) acc[f] = make_float2(0.f, 0.f);

            #pragma unroll
            for (int m = 0; m < 15; m++) {
                float2 pv = pl[m * POOL_CH_F2];
                #pragma unroll
                for (int f = 0; f < 16; f++) {
                    float w = __ldg(wl + m * 588 + f * 8820);
                    float2 r = ffma2(pv, make_float2(w, w), acc[f]);
                    acc[f] = act ? r : acc[f];     // predicated accumulate
                }
            }

            // select-butterfly: 16 sums over 32 lanes in 4 halving steps + 1
            {
                bool b = (lane & 16) != 0;
                #pragma unroll
                for (int f = 0; f < 8; f++) {
                    float2 snd = b ? acc[f] : acc[f + 8];
                    float rx = __shfl_xor_sync(0xffffffffu, snd.x, 16);
                    float ry = __shfl_xor_sync(0xffffffffu, snd.y, 16);
                    float2 kp = b ? acc[f + 8] : acc[f];
                    acc[f] = make_float2(kp.x + rx, kp.y + ry);
                }
            }
            {
                bool b = (lane & 8) != 0;
                #pragma unroll
                for (int f = 0; f < 4; f++) {
                    float2 snd = b ? acc[f] : acc[f + 4];
                    float rx = __shfl_xor_sync(0xffffffffu, snd.x, 8);
                    float ry = __shfl_xor_sync(0xffffffffu, snd.y, 8);
                    float2 kp = b ? acc[f + 4] : acc[f];
                    acc[f] = make_float2(kp.x + rx, kp.y + ry);
                }
            }
            {
                bool b = (lane & 4) != 0;
                #pragma unroll
                for (int f = 0; f < 2; f++) {
                    float2 snd = b ? acc[f] : acc[f + 2];
                    float rx = __shfl_xor_sync(0xffffffffu, snd.x, 4);
                    float ry = __shfl_xor_sync(0xffffffffu, snd.y, 4);
                    float2 kp = b ? acc[f + 2] : acc[f];
                    acc[f] = make_float2(kp.x + rx, kp.y + ry);
                }
            }
            {
                bool b = (lane & 2) != 0;
                float2 snd = b ? acc[0] : acc[1];
                float rx = __shfl_xor_sync(0xffffffffu, snd.x, 2);
                float ry = __shfl_xor_sync(0xffffffffu, snd.y, 2);
                float2 kp = b ? acc[1] : acc[0];
                acc[0] = make_float2(kp.x + rx, kp.y + ry);
            }
            acc[0].x += __shfl_xor_sync(0xffffffffu, acc[0].x, 1);
            acc[0].y += __shfl_xor_sync(0xffffffffu, acc[0].y, 1);

            // lane (f<<1) has f's sum; even lane stores img0, odd img1
            int f   = (lane >> 1) & 15;
            int idx = f * 21 + gi;
            float tb = tree_b[idx];
            if ((lane & 1) == 0)
                s_t[      idx] = sigmoidf_fast(acc[0].x + tb);
            else
                s_t[336 + idx] = sigmoidf_fast(acc[0].y + tb);
        }
    }
    __syncthreads();

    // ---- phase 3: FC 336 -> 10 ----
    if (tid < 160) {
        int part  = tid & 7;
        int combo = tid >> 3;
        int img   = combo / 10;
        int o     = combo % 10;
        const float* tv = s_t + img * 336;
        const float* wv = fc_w + o * 336;
        float s = 0.f;
        for (int k = part; k < 336; k += 8)
            s = fmaf(tv[k], wv[k], s);
        s += __shfl_xor_sync(0xffffffffu, s, 1);
        s += __shfl_xor_sync(0xffffffffu, s, 2);
        s += __shfl_xor_sync(0xffffffffu, s, 4);
        if (part == 0)
            out[(b0 + img) * 10 + o] = s + fc_b[o];
    }
}

extern "C" void kernel_launch(void* const* d_in, const int* in_sizes, int n_in,
                              void* d_out, int out_size)
{
    const float* x      = (const float*)d_in[0];
    const float* conv_w = (const float*)d_in[1];
    const float* conv_b = (const float*)d_in[2];
    const float* tree_w = (const float*)d_in[3];
    const float* tree_b = (const float*)d_in[4];
    const float* fc_w   = (const float*)d_in[5];
    const float* fc_b   = (const float*)d_in[6];
    float* out = (float*)d_out;

    const int smem_bytes = SMEM_FLOATS * (int)sizeof(float);
    cudaFuncSetAttribute(tree3_fused,
                         cudaFuncAttributeMaxDynamicSharedMemorySize, smem_bytes);

    tree3_fused<<<BTOT / 2, THREADS, smem_bytes>>>(
        x, conv_w, conv_b, tree_w, tree_b, fc_w, fc_b, out);
}

// round 14
// speedup vs baseline: 1.1510x; 1.0605x over previous
#include <cuda_runtime.h>

// ---------------------------------------------------------------------------
// Tree3 fused, round 14: R11 base +
//  - conv merged back to one 14-col pass (54 LDS.128/task, 6 stall points,
//    single weight-load sweep) -- R4 body, R11 pool layout
//  - phase-2 m-loop fully unrolled + pv prefetch, R11 predicated-load form
// ---------------------------------------------------------------------------

#define THREADS 256
#define BTOT 2048

// float2-unit strides
#define IMG_ROW_F2   34
#define IMG_PLANE_F2 1092
#define POOL_ROW_F2  15
#define POOL_CH_F2   211

#define SZ_IMG_F2    (3*IMG_PLANE_F2)
#define SZ_POOL_F2   (45*POOL_CH_F2)
#define OFF_POOL_F2  SZ_IMG_F2
#define OFF_W        (2*(SZ_IMG_F2 + SZ_POOL_F2))
#define OFF_CB       (OFF_W + 1128)
#define OFF_T        (OFF_CB + 48)
#define SMEM_FLOATS  (OFF_T + 2*336)

__device__ __forceinline__ float2 ffma2(float2 a, float2 b, float2 c) {
    unsigned long long au = *reinterpret_cast<unsigned long long*>(&a);
    unsigned long long bu = *reinterpret_cast<unsigned long long*>(&b);
    unsigned long long cu = *reinterpret_cast<unsigned long long*>(&c);
    unsigned long long du;
    asm("fma.rn.f32x2 %0, %1, %2, %3;" : "=l"(du) : "l"(au), "l"(bu), "l"(cu));
    return *reinterpret_cast<float2*>(&du);
}

__device__ __forceinline__ float sigmoidf_fast(float v) {
    return __fdividef(1.0f, 1.0f + __expf(-v));
}

// Full 14-column conv over an image pair: 6 input rows, rolling 2-row acc,
// single weight sweep. Produces 7 pooled pre-activation maxima.
__device__ __forceinline__ void conv_task14(const float2* __restrict__ ib,
                                            const float*  __restrict__ wb,
                                            float2* __restrict__ pmax)
{
    float2 acc0[14], acc1[14];
    #pragma unroll
    for (int k = 0; k < 14; k++) {
        acc0[k] = make_float2(0.f, 0.f);
        acc1[k] = make_float2(0.f, 0.f);
    }

    float2 wpk[5];
    #pragma unroll
    for (int r = 0; r < 6; r++) {
        float2 P[18];
        const float4* rp = (const float4*)(ib + r * IMG_ROW_F2);
        #pragma unroll
        for (int u = 0; u < 9; u++) {
            float4 q = rp[u];
            P[2*u]   = make_float2(q.x, q.y);
            P[2*u+1] = make_float2(q.z, q.w);
        }
        if (r > 0) {
            #pragma unroll
            for (int kx = 0; kx < 5; kx++)
                #pragma unroll
                for (int ox = 0; ox < 14; ox++)
                    acc1[ox] = ffma2(P[ox + kx], wpk[kx], acc1[ox]);
        }
        if (r < 5) {
            #pragma unroll
            for (int kx = 0; kx < 5; kx++) {
                float w = wb[r * 5 + kx];
                wpk[kx] = make_float2(w, w);
            }
            #pragma unroll
            for (int kx = 0; kx < 5; kx++)
                #pragma unroll
                for (int ox = 0; ox < 14; ox++)
                    acc0[ox] = ffma2(P[ox + kx], wpk[kx], acc0[ox]);
        }
    }

    #pragma unroll
    for (int pj = 0; pj < 7; pj++) {
        float vx = fmaxf(fmaxf(acc0[2*pj].x, acc0[2*pj+1].x),
                         fmaxf(acc1[2*pj].x, acc1[2*pj+1].x));
        float vy = fmaxf(fmaxf(acc0[2*pj].y, acc0[2*pj+1].y),
                         fmaxf(acc1[2*pj].y, acc1[2*pj+1].y));
        pmax[pj] = make_float2(vx, vy);
    }
}

__global__ __launch_bounds__(THREADS, 2)
void tree3_fused(const float* __restrict__ x,
                 const float* __restrict__ conv_w,
                 const float* __restrict__ conv_b,
                 const float* __restrict__ tree_w,
                 const float* __restrict__ tree_b,
                 const float* __restrict__ fc_w,
                 const float* __restrict__ fc_b,
                 float* __restrict__ out)
{
    extern __shared__ __align__(16) float sm[];
    float2* s_img  = reinterpret_cast<float2*>(sm);
    float2* s_pool = reinterpret_cast<float2*>(sm) + OFF_POOL_F2;
    float*  s_w    = sm + OFF_W;
    float*  s_cb   = sm + OFF_CB;
    float*  s_t    = sm + OFF_T;

    const int tid  = threadIdx.x;
    const int lane = tid & 31;
    const int wid  = tid >> 5;
    const int b0   = blockIdx.x * 2;

    // ---- stage conv weights + bias ----
    for (int idx = tid; idx < 1125; idx += THREADS) s_w[idx] = conv_w[idx];
    if (tid < 45) s_cb[tid] = conv_b[tid];

    // ---- stage the image pair, interleaved (float4 in/out) ----
    for (int idx = tid; idx < 3 * 32 * 8; idx += THREADS) {
        int grp = idx & 7;
        int row = (idx >> 3) & 31;
        int gch = idx >> 8;
        const float* pA = x + (size_t)b0 * 3072 + gch * 1024 + row * 32 + grp * 4;
        float4 a = *(const float4*)pA;
        float4 b = *(const float4*)(pA + 3072);
        float4* dst = (float4*)(s_img + gch * IMG_PLANE_F2
                                      + row * IMG_ROW_F2 + grp * 4);
        dst[0] = make_float4(a.x, b.x, a.y, b.y);
        dst[1] = make_float4(a.z, b.z, a.w, b.w);
    }
    __syncthreads();

    // ---- phase 1: packed conv + sigmoid(max-pool), single 14-col pass ----
    for (int task = tid; task < 45 * 28; task += THREADS) {
        int c    = task % 45;
        int rest = task / 45;
        int half = rest & 1;
        int pi   = rest >> 1;

        int g  = c / 15;
        const float*  wb = s_w + c * 25;
        const float2* ib = s_img + g * IMG_PLANE_F2
                                 + (pi * 2) * IMG_ROW_F2 + half * 14;

        float2 pmax[7];
        conv_task14(ib, wb, pmax);

        float bias = s_cb[c];
        float2* pb = s_pool + c * POOL_CH_F2 + pi * POOL_ROW_F2 + half * 7;
        #pragma unroll
        for (int pj = 0; pj < 7; pj++)
            pb[pj] = make_float2(sigmoidf_fast(pmax[pj].x + bias),
                                 sigmoidf_fast(pmax[pj].y + bias));
    }
    __syncthreads();

    // ---- phase 2: tree einsum, one warp per gi, lanes = (j,ki,kj) ----
    {
        const bool act = lane < 28;
        const int jr  = lane >> 2;
        const int j   = (jr > 6) ? 6 : jr;       // keep tail-lane addrs in-bounds
        const int ki  = (lane >> 1) & 1;
        const int kj  = lane & 1;

        for (int gi = wid; gi < 21; gi += THREADS / 32) {
            int g = gi / 7;
            int i = gi % 7;

            const float* wl = tree_w + g * 196 + i * 28 + j * 4 + ki * 2 + kj;
            const float2* pl = s_pool + (g * 15) * POOL_CH_F2
                             + (2 * i + ki) * POOL_ROW_F2 + 2 * j + kj;

            float2 acc[16];
            #pragma unroll
            for (int f = 0; f < 16; f++) acc[f] = make_float2(0.f, 0.f);

            float2 pv = pl[0];
            #pragma unroll
            for (int m = 0; m < 15; m++) {
                float2 pv_next = (m < 14) ? pl[(m + 1) * POOL_CH_F2] : pv;
                #pragma unroll
                for (int f = 0; f < 16; f++) {
                    float w = act ? __ldg(wl + m * 588 + f * 8820) : 0.f;
                    acc[f] = ffma2(pv, make_float2(w, w), acc[f]);
                }
                pv = pv_next;
            }

            // select-butterfly: 16 sums over 32 lanes in 4 halving steps + 1
            {
                bool b = (lane & 16) != 0;
                #pragma unroll
                for (int f = 0; f < 8; f++) {
                    float2 snd = b ? acc[f] : acc[f + 8];
                    float rx = __shfl_xor_sync(0xffffffffu, snd.x, 16);
                    float ry = __shfl_xor_sync(0xffffffffu, snd.y, 16);
                    float2 kp = b ? acc[f + 8] : acc[f];
                    acc[f] = make_float2(kp.x + rx, kp.y + ry);
                }
            }
            {
                bool b = (lane & 8) != 0;
                #pragma unroll
                for (int f = 0; f < 4; f++) {
                    float2 snd = b ? acc[f] : acc[f + 4];
                    float rx = __shfl_xor_sync(0xffffffffu, snd.x, 8);
                    float ry = __shfl_xor_sync(0xffffffffu, snd.y, 8);
                    float2 kp = b ? acc[f + 4] : acc[f];
                    acc[f] = make_float2(kp.x + rx, kp.y + ry);
                }
            }
            {
                bool b = (lane & 4) != 0;
                #pragma unroll
                for (int f = 0; f < 2; f++) {
                    float2 snd = b ? acc[f] : acc[f + 2];
                    float rx = __shfl_xor_sync(0xffffffffu, snd.x, 4);
                    float ry = __shfl_xor_sync(0xffffffffu, snd.y, 4);
                    float2 kp = b ? acc[f + 2] : acc[f];
                    acc[f] = make_float2(kp.x + rx, kp.y + ry);
                }
            }
            {
                bool b = (lane & 2) != 0;
                float2 snd = b ? acc[0] : acc[1];
                float rx = __shfl_xor_sync(0xffffffffu, snd.x, 2);
                float ry = __shfl_xor_sync(0xffffffffu, snd.y, 2);
                float2 kp = b ? acc[1] : acc[0];
                acc[0] = make_float2(kp.x + rx, kp.y + ry);
            }
            acc[0].x += __shfl_xor_sync(0xffffffffu, acc[0].x, 1);
            acc[0].y += __shfl_xor_sync(0xffffffffu, acc[0].y, 1);

            // lane (f<<1) has f's sum; even lane stores img0, odd img1
            int f   = (lane >> 1) & 15;
            int idx = f * 21 + gi;
            float tb = tree_b[idx];
            if ((lane & 1) == 0)
                s_t[      idx] = sigmoidf_fast(acc[0].x + tb);
            else
                s_t[336 + idx] = sigmoidf_fast(acc[0].y + tb);
        }
    }
    __syncthreads();

    // ---- phase 3: FC 336 -> 10 ----
    if (tid < 160) {
        int part  = tid & 7;
        int combo = tid >> 3;
        int img   = combo / 10;
        int o     = combo % 10;
        const float* tv = s_t + img * 336;
        const float* wv = fc_w + o * 336;
        float s = 0.f;
        for (int k = part; k < 336; k += 8)
            s = fmaf(tv[k], wv[k], s);
        s += __shfl_xor_sync(0xffffffffu, s, 1);
        s += __shfl_xor_sync(0xffffffffu, s, 2);
        s += __shfl_xor_sync(0xffffffffu, s, 4);
        if (part == 0)
            out[(b0 + img) * 10 + o] = s + fc_b[o];
    }
}

extern "C" void kernel_launch(void* const* d_in, const int* in_sizes, int n_in,
                              void* d_out, int out_size)
{
    const float* x      = (const float*)d_in[0];
    const float* conv_w = (const float*)d_in[1];
    const float* conv_b = (const float*)d_in[2];
    const float* tree_w = (const float*)d_in[3];
    const float* tree_b = (const float*)d_in[4];
    const float* fc_w   = (const float*)d_in[5];
    const float* fc_b   = (const float*)d_in[6];
    float* out = (float*)d_out;

    const int smem_bytes = SMEM_FLOATS * (int)sizeof(float);
    cudaFuncSetAttribute(tree3_fused,
                         cudaFuncAttributeMaxDynamicSharedMemorySize, smem_bytes);

    tree3_fused<<<BTOT / 2, THREADS, smem_bytes>>>(
        x, conv_w, conv_b, tree_w, tree_b, fc_w, fc_b, out);
}